// round 16
// baseline (speedup 1.0000x reference)
#include <cuda_runtime.h>
#include <cuda_bf16.h>
#include <stdint.h>

// Scatter-add F_st[e] * edge_vec[e] into out[edge_idx[e]], n_atoms x 3.
//
// Architecture: two kernels overlapped with PDL + EARLY TRIGGER.
//  - scatter: R1 shape (4 edges/thread, all LDG.128, one thread per quad,
//    max grid). L1tex-wavefront-bound by the 6.4M scattered RED.128 lanes
//    (~128 of ~148 wavefronts per warp); pinned at ~44us across R1-R14.
//    Each block fences + calls cudaTriggerProgrammaticLaunchCompletion()
//    right after its REDs, so the secondary's gate releases at last-trigger
//    (not kernel retirement) and its rollout overlaps the primary's drain.
//  - epilogue: PDL secondary (GPB=32 -> 782 blocks, measured best);
//    cudaGridDependencySynchronize() (HW-backed) then float4 copy+zero.
//
// Every second graph node costs ~4-6us of launch floor regardless of body
// (measured R1-R14); the early trigger is aimed at hiding that floor.
//
// g_acc is 16B-padded so each edge is ONE red.global.add.v4.f32. The
// epilogue compacts [n,4]->[n,3] into d_out AND resets g_acc, maintaining
// the zero-on-entry invariant (device globals start zeroed).

#define MAX_ATOMS 100000
#define TB  256
#define GPB 32                 // groups per block (96 copy threads of 256)

__device__ float4 g_acc[MAX_ATOMS];

__device__ __forceinline__ void red_add_v4(float4* p, float x, float y, float z) {
    asm volatile("red.global.add.v4.f32 [%0], {%1, %2, %3, %4};"
                 :: "l"(p), "f"(x), "f"(y), "f"(z), "f"(0.0f) : "memory");
}

// 4 edges per thread, all loads LDG.128, fully parallel grid.
__global__ __launch_bounds__(TB)
void scatter_kernel(const float4* __restrict__ F4,
                    const float4* __restrict__ V4,
                    const int4*   __restrict__ I4,
                    int nq, int n_edges) {
    int t = blockIdx.x * TB + threadIdx.x;
    if (t < nq) {
        float4 f  = F4[t];
        float4 a  = V4[3 * t + 0];
        float4 b  = V4[3 * t + 1];
        float4 c  = V4[3 * t + 2];
        int4   id = I4[t];

        // e0=(a.x,a.y,a.z) e1=(a.w,b.x,b.y) e2=(b.z,b.w,c.x) e3=(c.y,c.z,c.w)
        red_add_v4(&g_acc[id.x], f.x * a.x, f.x * a.y, f.x * a.z);
        red_add_v4(&g_acc[id.y], f.y * a.w, f.y * b.x, f.y * b.y);
        red_add_v4(&g_acc[id.z], f.z * b.z, f.z * b.w, f.z * c.x);
        red_add_v4(&g_acc[id.w], f.w * c.y, f.w * c.z, f.w * c.w);
    } else if (t == nq) {
        // scalar tail (n_edges % 4 edges), exactly one thread
        const float* F   = (const float*)F4;
        const float* V   = (const float*)V4;
        const int*   IDX = (const int*)I4;
        for (int e = 4 * nq; e < n_edges; e++) {
            float fe = F[e];
            int   i  = IDX[e];
            red_add_v4(&g_acc[i], fe * V[3 * e + 0], fe * V[3 * e + 1],
                       fe * V[3 * e + 2]);
        }
    }

    // Write -> fence -> trigger (documented PDL pattern): this block's REDs
    // are visible to the secondary after its gridDependencySynchronize.
    __threadfence();
    cudaTriggerProgrammaticLaunchCompletion();
}

// Compact [n,4] -> [n,3] into d_out and reset g_acc. PDL secondary.
// group g covers atoms [4g,4g+4) and out float4s [3g,3g+3):
//   r=0: out4[3g+0] = (A0.x,A0.y,A0.z,A1.x)   loads acc[4g],  acc[4g+1]
//   r=1: out4[3g+1] = (A1.y,A1.z,A2.x,A2.y)   loads acc[4g+1],acc[4g+2]
//   r=2: out4[3g+2] = (A2.z,A3.x,A3.y,A3.z)   loads acc[4g+2],acc[4g+3]
__global__ __launch_bounds__(TB)
void copy_zero_pdl(float4* __restrict__ out4, int n_atoms) {
    // Address math first (independent of primary's results).
    int n_groups = n_atoms >> 2;
    int g0 = blockIdx.x * GPB;
    int ml = threadIdx.x;
    int g  = g0 + ml / 3;
    int r  = ml - 3 * (ml / 3);
    bool active = (ml < 3 * GPB) && (g < n_groups);

    // HW-backed wait: all scatter blocks have fenced + triggered.
    cudaGridDependencySynchronize();

    float4 lo, hi;
    if (active) {
        int a = 4 * g + r;
        lo = g_acc[a];          // two independent LDG.128 (MLP=2)
        hi = g_acc[a + 1];
    }

    __syncthreads();            // all block reads done before block zeroes

    if (active) {
        float4 o;
        if (r == 0)      o = make_float4(lo.x, lo.y, lo.z, hi.x);
        else if (r == 1) o = make_float4(lo.y, lo.z, hi.x, hi.y);
        else             o = make_float4(lo.z, hi.x, hi.y, hi.z);
        out4[3 * g + r] = o;    // coalesced STG.128
    }

    // Zero the block-owned acc range: pure STG.128, issue-only cost.
    int a_begin = 4 * g0;
    int a_end   = 4 * min(g0 + GPB, n_groups);
    float4 z = make_float4(0.f, 0.f, 0.f, 0.f);
    for (int a = a_begin + ml; a < a_end; a += TB)
        g_acc[a] = z;

    // Global tail: atoms beyond the last full group (none for n_atoms % 4 == 0).
    if (blockIdx.x == 0 && ml == 0) {
        float* out = reinterpret_cast<float*>(out4);
        for (int at = 4 * n_groups; at < n_atoms; at++) {
            float4 v = g_acc[at];
            g_acc[at] = z;
            out[3 * at + 0] = v.x;
            out[3 * at + 1] = v.y;
            out[3 * at + 2] = v.z;
        }
    }
}

extern "C" void kernel_launch(void* const* d_in, const int* in_sizes, int n_in,
                              void* d_out, int out_size) {
    const float4* F4 = (const float4*)d_in[0];   // F_st     [E,1] f32
    const float4* V4 = (const float4*)d_in[1];   // edge_vec [E,3] f32
    const int4*   I4 = (const int4*)d_in[2];     // edge_idx [E]   i32
    float4* out4 = (float4*)d_out;               // [n_atoms,3] f32

    int n_edges = in_sizes[0];
    int n_atoms = out_size / 3;
    if (n_atoms > MAX_ATOMS) n_atoms = MAX_ATOMS;

    int nq = n_edges / 4;

    // Primary: scatter. nq+1 threads (extra thread = scalar tail).
    scatter_kernel<<<(nq + 1 + TB - 1) / TB, TB>>>(F4, V4, I4, nq, n_edges);

    // Secondary: epilogue with programmatic dependent launch.
    int n_groups = n_atoms / 4;
    int nblocks  = (n_groups + GPB - 1) / GPB;
    if (nblocks < 1) nblocks = 1;

    cudaLaunchConfig_t cfg = {};
    cfg.gridDim  = dim3((unsigned)nblocks, 1, 1);
    cfg.blockDim = dim3(TB, 1, 1);
    cfg.dynamicSmemBytes = 0;
    cfg.stream = 0;                               // same stream as primary
    cudaLaunchAttribute attr[1];
    attr[0].id = cudaLaunchAttributeProgrammaticStreamSerialization;
    attr[0].val.programmaticStreamSerializationAllowed = 1;
    cfg.attrs = attr;
    cfg.numAttrs = 1;

    cudaLaunchKernelEx(&cfg, copy_zero_pdl, out4, n_atoms);
}

// round 17
// speedup vs baseline: 1.0423x; 1.0423x over previous
#include <cuda_runtime.h>
#include <cuda_bf16.h>
#include <stdint.h>

// Scatter-add F_st[e] * edge_vec[e] into out[edge_idx[e]], n_atoms x 3.
//
// FINAL (locked, best measured = 49.3us over 16 rounds):
//  - scatter: 4 edges/thread, all LDG.128, one thread per quad, max grid.
//    Pinned at ~43.5-45.5us by scattered-REDG wavefront/latency floor (6.4M
//    red.global.add.v4.f32 lanes); every load-path, occupancy, and fusion
//    variant tried (R1-R15) landed in-band or worse.
//  - epilogue: PDL secondary, DEFAULT trigger (release at primary retirement
//    — an early trigger parks secondary blocks in scatter slots and costs
//    +2us, measured R15). cudaGridDependencySynchronize() then float4
//    copy+zero, GPB=85 (295 blocks, measured best at 49.28).
//
// g_acc is 16B-padded so each edge is ONE vec4 RED (1 LSU lane vs 3 scalar).
// The epilogue compacts [n,4]->[n,3] into d_out AND resets g_acc,
// maintaining the zero-on-entry invariant (device globals start zeroed).

#define MAX_ATOMS 100000
#define TB  256
#define GPB 85                 // groups per block (255 copy threads of 256)

__device__ float4 g_acc[MAX_ATOMS];

__device__ __forceinline__ void red_add_v4(float4* p, float x, float y, float z) {
    asm volatile("red.global.add.v4.f32 [%0], {%1, %2, %3, %4};"
                 :: "l"(p), "f"(x), "f"(y), "f"(z), "f"(0.0f) : "memory");
}

// 4 edges per thread, all loads LDG.128, fully parallel grid.
__global__ __launch_bounds__(TB)
void scatter_kernel(const float4* __restrict__ F4,
                    const float4* __restrict__ V4,
                    const int4*   __restrict__ I4,
                    int nq, int n_edges) {
    int t = blockIdx.x * TB + threadIdx.x;
    if (t < nq) {
        float4 f  = F4[t];
        float4 a  = V4[3 * t + 0];
        float4 b  = V4[3 * t + 1];
        float4 c  = V4[3 * t + 2];
        int4   id = I4[t];

        // e0=(a.x,a.y,a.z) e1=(a.w,b.x,b.y) e2=(b.z,b.w,c.x) e3=(c.y,c.z,c.w)
        red_add_v4(&g_acc[id.x], f.x * a.x, f.x * a.y, f.x * a.z);
        red_add_v4(&g_acc[id.y], f.y * a.w, f.y * b.x, f.y * b.y);
        red_add_v4(&g_acc[id.z], f.z * b.z, f.z * b.w, f.z * c.x);
        red_add_v4(&g_acc[id.w], f.w * c.y, f.w * c.z, f.w * c.w);
    } else if (t == nq) {
        // scalar tail (n_edges % 4 edges), exactly one thread
        const float* F   = (const float*)F4;
        const float* V   = (const float*)V4;
        const int*   IDX = (const int*)I4;
        for (int e = 4 * nq; e < n_edges; e++) {
            float fe = F[e];
            int   i  = IDX[e];
            red_add_v4(&g_acc[i], fe * V[3 * e + 0], fe * V[3 * e + 1],
                       fe * V[3 * e + 2]);
        }
    }
}

// Compact [n,4] -> [n,3] into d_out and reset g_acc. PDL secondary: waits on
// the scatter via cudaGridDependencySynchronize() (HW-backed; releases at
// primary retirement under the default implicit trigger).
// group g covers atoms [4g,4g+4) and out float4s [3g,3g+3):
//   r=0: out4[3g+0] = (A0.x,A0.y,A0.z,A1.x)   loads acc[4g],  acc[4g+1]
//   r=1: out4[3g+1] = (A1.y,A1.z,A2.x,A2.y)   loads acc[4g+1],acc[4g+2]
//   r=2: out4[3g+2] = (A2.z,A3.x,A3.y,A3.z)   loads acc[4g+2],acc[4g+3]
__global__ __launch_bounds__(TB)
void copy_zero_pdl(float4* __restrict__ out4, int n_atoms) {
    // Address math first (independent of primary's results).
    int n_groups = n_atoms >> 2;
    int g0 = blockIdx.x * GPB;
    int ml = threadIdx.x;
    int g  = g0 + ml / 3;
    int r  = ml - 3 * (ml / 3);
    bool active = (ml < 3 * GPB) && (g < n_groups);

    // HW-backed wait: all scatter REDs visible after this returns.
    cudaGridDependencySynchronize();

    float4 lo, hi;
    if (active) {
        int a = 4 * g + r;
        lo = g_acc[a];          // two independent LDG.128 (MLP=2)
        hi = g_acc[a + 1];
    }

    __syncthreads();            // all block reads done before block zeroes

    if (active) {
        float4 o;
        if (r == 0)      o = make_float4(lo.x, lo.y, lo.z, hi.x);
        else if (r == 1) o = make_float4(lo.y, lo.z, hi.x, hi.y);
        else             o = make_float4(lo.z, hi.x, hi.y, hi.z);
        out4[3 * g + r] = o;    // coalesced STG.128
    }

    // Zero the block-owned acc range: pure STG.128, issue-only cost.
    int a_begin = 4 * g0;
    int a_end   = 4 * min(g0 + GPB, n_groups);
    float4 z = make_float4(0.f, 0.f, 0.f, 0.f);
    for (int a = a_begin + ml; a < a_end; a += TB)
        g_acc[a] = z;

    // Global tail: atoms beyond the last full group (none for n_atoms % 4 == 0).
    if (blockIdx.x == 0 && ml == 0) {
        float* out = reinterpret_cast<float*>(out4);
        for (int at = 4 * n_groups; at < n_atoms; at++) {
            float4 v = g_acc[at];
            g_acc[at] = z;
            out[3 * at + 0] = v.x;
            out[3 * at + 1] = v.y;
            out[3 * at + 2] = v.z;
        }
    }
}

extern "C" void kernel_launch(void* const* d_in, const int* in_sizes, int n_in,
                              void* d_out, int out_size) {
    const float4* F4 = (const float4*)d_in[0];   // F_st     [E,1] f32
    const float4* V4 = (const float4*)d_in[1];   // edge_vec [E,3] f32
    const int4*   I4 = (const int4*)d_in[2];     // edge_idx [E]   i32
    float4* out4 = (float4*)d_out;               // [n_atoms,3] f32

    int n_edges = in_sizes[0];
    int n_atoms = out_size / 3;
    if (n_atoms > MAX_ATOMS) n_atoms = MAX_ATOMS;

    int nq = n_edges / 4;

    // Primary: scatter. nq+1 threads (extra thread = scalar tail).
    scatter_kernel<<<(nq + 1 + TB - 1) / TB, TB>>>(F4, V4, I4, nq, n_edges);

    // Secondary: epilogue with programmatic dependent launch.
    int n_groups = n_atoms / 4;
    int nblocks  = (n_groups + GPB - 1) / GPB;
    if (nblocks < 1) nblocks = 1;

    cudaLaunchConfig_t cfg = {};
    cfg.gridDim  = dim3((unsigned)nblocks, 1, 1);
    cfg.blockDim = dim3(TB, 1, 1);
    cfg.dynamicSmemBytes = 0;
    cfg.stream = 0;                               // same stream as primary
    cudaLaunchAttribute attr[1];
    attr[0].id = cudaLaunchAttributeProgrammaticStreamSerialization;
    attr[0].val.programmaticStreamSerializationAllowed = 1;
    cfg.attrs = attr;
    cfg.numAttrs = 1;

    cudaLaunchKernelEx(&cfg, copy_zero_pdl, out4, n_atoms);
}